// round 1
// baseline (speedup 1.0000x reference)
#include <cuda_runtime.h>
#include <math.h>

// Problem constants (shapes fixed by the reference)
#define MAXN 100000
#define MAXE 1600000
#define MAXT (MAXN + MAXE)   // edges + self loops

// ---------------- static device scratch (no allocations allowed) -------------
__device__ __align__(16) float g_h1  [MAXN * 64];   // layer1 features per node
__device__ __align__(16) float g_as1 [MAXN * 4];    // alpha_src layer1 [N,H]
__device__ __align__(16) float g_ad1 [MAXN * 4];    // alpha_dst layer1 [N,H]
__device__ __align__(16) float g_e1  [MAXT * 4];    // exp(e) per edge, layer1
__device__ __align__(16) float g_den1[MAXN * 4];    // softmax denominators
__device__ __align__(16) float g_agg1[MAXN * 64];   // aggregated layer1 output
__device__ __align__(16) float g_h2  [MAXN * 40];   // layer2 features per node
__device__            float g_as2 [MAXN];
__device__            float g_ad2 [MAXN];
__device__            float g_e2  [MAXT];
__device__            float g_den2[MAXN];
__device__ __align__(16) float g_agg2[MAXN * 40];

__device__ __forceinline__ float lrelu(float v) { return v > 0.f ? v : 0.2f * v; }

// ---------------- kernel 0: zero the accumulators ---------------------------
__global__ void k_init(int n) {
    int i = blockIdx.x * blockDim.x + threadIdx.x;
    int stride = gridDim.x * blockDim.x;
    for (int k = i; k < n * 4;  k += stride) g_den1[k] = 0.f;
    for (int k = i; k < n * 64; k += stride) g_agg1[k] = 0.f;
    for (int k = i; k < n;      k += stride) g_den2[k] = 0.f;
    for (int k = i; k < n * 40; k += stride) g_agg2[k] = 0.f;
}

// ---------------- kernel 1: h1 = x @ W1^T, plus alpha_s/alpha_d --------------
// W1: [64,128].  One warp per row; W1 transposed into smem once per block.
__global__ void k_gemm1(const float* __restrict__ x, const float* __restrict__ W1,
                        const float* __restrict__ a_s, const float* __restrict__ a_d,
                        int n) {
    __shared__ float Wt[128 * 64];   // Wt[k*64 + c] = W1[c*128 + k]
    int tid = threadIdx.x;
    for (int i = tid; i < 128 * 64; i += blockDim.x) {
        int c = i >> 7, k = i & 127;
        Wt[k * 64 + c] = W1[i];
    }
    __syncthreads();

    int lane   = tid & 31;
    int warp   = (blockIdx.x * blockDim.x + tid) >> 5;
    int nwarps = (gridDim.x * blockDim.x) >> 5;

    for (int row = warp; row < n; row += nwarps) {
        const float* xr = x + (size_t)row * 128;
        float xv[4];
        xv[0] = xr[lane]; xv[1] = xr[lane + 32]; xv[2] = xr[lane + 64]; xv[3] = xr[lane + 96];
        float acc0 = 0.f, acc1 = 0.f;
        #pragma unroll
        for (int kk = 0; kk < 4; kk++) {
            float xsrc = xv[kk];
            #pragma unroll
            for (int l = 0; l < 32; l++) {
                float xk = __shfl_sync(0xffffffffu, xsrc, l);
                int k = kk * 32 + l;
                acc0 = fmaf(Wt[k * 64 + lane],      xk, acc0);
                acc1 = fmaf(Wt[k * 64 + lane + 32], xk, acc1);
            }
        }
        g_h1[(size_t)row * 64 + lane]      = acc0;
        g_h1[(size_t)row * 64 + lane + 32] = acc1;

        // alphas: acc0 covers channels [0,32) -> heads 0,1 ; acc1 -> heads 2,3
        float ps0 = acc0 * a_s[lane], ps1 = acc1 * a_s[lane + 32];
        float pd0 = acc0 * a_d[lane], pd1 = acc1 * a_d[lane + 32];
        #pragma unroll
        for (int off = 8; off; off >>= 1) {
            ps0 += __shfl_down_sync(0xffffffffu, ps0, off, 16);
            ps1 += __shfl_down_sync(0xffffffffu, ps1, off, 16);
            pd0 += __shfl_down_sync(0xffffffffu, pd0, off, 16);
            pd1 += __shfl_down_sync(0xffffffffu, pd1, off, 16);
        }
        if ((lane & 15) == 0) {
            int head = lane >> 4;                   // 0 or 1
            g_as1[row * 4 + head]     = ps0;
            g_as1[row * 4 + head + 2] = ps1;
            g_ad1[row * 4 + head]     = pd0;
            g_ad1[row * 4 + head + 2] = pd1;
        }
    }
}

// ---------------- kernel 2: per-edge exp + denominator (layer1) --------------
__global__ void k_edgeB1(const int* __restrict__ ei, int e, int n) {
    int t = blockIdx.x * blockDim.x + threadIdx.x;
    if (t >= e + n) return;
    int src, dst;
    if (t < e) { src = ei[t]; dst = ei[e + t]; } else { src = dst = t - e; }
    float4 s = *(const float4*)&g_as1[src * 4];
    float4 d = *(const float4*)&g_ad1[dst * 4];
    float4 ex;
    ex.x = __expf(lrelu(s.x + d.x));
    ex.y = __expf(lrelu(s.y + d.y));
    ex.z = __expf(lrelu(s.z + d.z));
    ex.w = __expf(lrelu(s.w + d.w));
    *(float4*)&g_e1[(size_t)t * 4] = ex;
    atomicAdd((float4*)&g_den1[dst * 4], ex);
}

// ---------------- kernel 3: edge aggregation (layer1) ------------------------
// 16 threads per edge, one float4 (4 channels) each.
__global__ void k_aggC1(const int* __restrict__ ei, int e, int n) {
    int t = blockIdx.x * blockDim.x + threadIdx.x;
    int edge = t >> 4;
    if (edge >= e + n) return;
    int j = t & 15;
    int src, dst;
    if (edge < e) { src = ei[edge]; dst = ei[e + edge]; } else { src = dst = edge - e; }
    int head = j >> 2;
    float coef = __fdividef(g_e1[(size_t)edge * 4 + head], g_den1[dst * 4 + head]);
    float4 h = *(const float4*)&g_h1[(size_t)src * 64 + j * 4];
    float4 v = make_float4(h.x * coef, h.y * coef, h.z * coef, h.w * coef);
    atomicAdd((float4*)&g_agg1[(size_t)dst * 64 + j * 4], v);
}

// ---------------- kernel 4: relu + h2 = relu(agg1+b1) @ W2^T + alpha2 --------
// W2: [40,64]. One warp per row.
__global__ void k_gemm2(const float* __restrict__ b1, const float* __restrict__ W2,
                        const float* __restrict__ a_s, const float* __restrict__ a_d,
                        int n) {
    __shared__ float Wt[64 * 40];  // Wt[k*40 + c] = W2[c*64 + k]
    __shared__ float sa[40], sd[40];
    int tid = threadIdx.x;
    for (int i = tid; i < 40 * 64; i += blockDim.x) {
        int c = i / 64, k = i - c * 64;
        Wt[k * 40 + c] = W2[i];
    }
    if (tid < 40) { sa[tid] = a_s[tid]; sd[tid] = a_d[tid]; }
    __syncthreads();

    int lane   = tid & 31;
    int warp   = (blockIdx.x * blockDim.x + tid) >> 5;
    int nwarps = (gridDim.x * blockDim.x) >> 5;

    for (int row = warp; row < n; row += nwarps) {
        float v0 = fmaxf(g_agg1[(size_t)row * 64 + lane]      + b1[lane],      0.f);
        float v1 = fmaxf(g_agg1[(size_t)row * 64 + lane + 32] + b1[lane + 32], 0.f);
        float acc0 = 0.f, acc1 = 0.f;
        #pragma unroll
        for (int k = 0; k < 64; k++) {
            float xk = (k < 32) ? __shfl_sync(0xffffffffu, v0, k)
                                : __shfl_sync(0xffffffffu, v1, k - 32);
            acc0 = fmaf(Wt[k * 40 + lane], xk, acc0);
            if (lane < 8) acc1 = fmaf(Wt[k * 40 + lane + 32], xk, acc1);
        }
        g_h2[(size_t)row * 40 + lane] = acc0;
        if (lane < 8) g_h2[(size_t)row * 40 + 32 + lane] = acc1;

        float ps = acc0 * sa[lane] + (lane < 8 ? acc1 * sa[lane + 32] : 0.f);
        float pd = acc0 * sd[lane] + (lane < 8 ? acc1 * sd[lane + 32] : 0.f);
        #pragma unroll
        for (int off = 16; off; off >>= 1) {
            ps += __shfl_xor_sync(0xffffffffu, ps, off);
            pd += __shfl_xor_sync(0xffffffffu, pd, off);
        }
        if (lane == 0) { g_as2[row] = ps; g_ad2[row] = pd; }
    }
}

// ---------------- kernel 5: per-edge exp + denominator (layer2) --------------
__global__ void k_edgeB2(const int* __restrict__ ei, int e, int n) {
    int t = blockIdx.x * blockDim.x + threadIdx.x;
    if (t >= e + n) return;
    int src, dst;
    if (t < e) { src = ei[t]; dst = ei[e + t]; } else { src = dst = t - e; }
    float ex = __expf(lrelu(g_as2[src] + g_ad2[dst]));
    g_e2[t] = ex;
    atomicAdd(&g_den2[dst], ex);
}

// ---------------- kernel 6: edge aggregation (layer2) ------------------------
// 16 threads per edge, 10 active (40 channels / float4).
__global__ void k_aggC2(const int* __restrict__ ei, int e, int n) {
    int t = blockIdx.x * blockDim.x + threadIdx.x;
    int edge = t >> 4;
    if (edge >= e + n) return;
    int j = t & 15;
    if (j >= 10) return;
    int src, dst;
    if (edge < e) { src = ei[edge]; dst = ei[e + edge]; } else { src = dst = edge - e; }
    float coef = __fdividef(g_e2[edge], g_den2[dst]);
    float4 h = *(const float4*)&g_h2[(size_t)src * 40 + j * 4];
    float4 v = make_float4(h.x * coef, h.y * coef, h.z * coef, h.w * coef);
    atomicAdd((float4*)&g_agg2[(size_t)dst * 40 + j * 4], v);
}

// ---------------- kernel 7: bias + log_softmax -> out ------------------------
__global__ void k_final(const float* __restrict__ b2, float* __restrict__ out, int n) {
    int lane = threadIdx.x & 31;
    int row  = (blockIdx.x * blockDim.x + threadIdx.x) >> 5;
    if (row >= n) return;
    float v0 = g_agg2[(size_t)row * 40 + lane] + b2[lane];
    float v1 = (lane < 8) ? (g_agg2[(size_t)row * 40 + 32 + lane] + b2[32 + lane]) : -1e30f;
    float m = fmaxf(v0, v1);
    #pragma unroll
    for (int off = 16; off; off >>= 1) m = fmaxf(m, __shfl_xor_sync(0xffffffffu, m, off));
    float s = __expf(v0 - m) + (lane < 8 ? __expf(v1 - m) : 0.f);
    #pragma unroll
    for (int off = 16; off; off >>= 1) s += __shfl_xor_sync(0xffffffffu, s, off);
    float ls = m + logf(s);
    out[(size_t)row * 40 + lane] = v0 - ls;
    if (lane < 8) out[(size_t)row * 40 + 32 + lane] = v1 - ls;
}

// ---------------- launcher ---------------------------------------------------
extern "C" void kernel_launch(void* const* d_in, const int* in_sizes, int n_in,
                              void* d_out, int out_size) {
    const float* x      = (const float*)d_in[0];
    const int*   ei     = (const int*)  d_in[1];
    const float* W1     = (const float*)d_in[2];
    const float* a_src1 = (const float*)d_in[3];
    const float* a_dst1 = (const float*)d_in[4];
    const float* b1     = (const float*)d_in[5];
    const float* W2     = (const float*)d_in[6];
    const float* a_src2 = (const float*)d_in[7];
    const float* a_dst2 = (const float*)d_in[8];
    const float* b2     = (const float*)d_in[9];
    float* out = (float*)d_out;

    int n = in_sizes[0] / 128;   // nodes
    int e = in_sizes[1] / 2;     // edges (before self loops)
    int total = e + n;

    k_init<<<2048, 256>>>(n);
    k_gemm1<<<1024, 256>>>(x, W1, a_src1, a_dst1, n);
    k_edgeB1<<<(total + 255) / 256, 256>>>(ei, e, n);
    {
        long long th = (long long)total * 16;
        k_aggC1<<<(unsigned)((th + 255) / 256), 256>>>(ei, e, n);
    }
    k_gemm2<<<1024, 256>>>(b1, W2, a_src2, a_dst2, n);
    k_edgeB2<<<(total + 255) / 256, 256>>>(ei, e, n);
    {
        long long th = (long long)total * 16;
        k_aggC2<<<(unsigned)((th + 255) / 256), 256>>>(ei, e, n);
    }
    k_final<<<(n * 32 + 255) / 256, 256>>>(b2, out, n);
}

// round 3
// speedup vs baseline: 1.0313x; 1.0313x over previous
#include <cuda_runtime.h>
#include <math.h>

#define MAXN 100000
#define MAXE 1600000
#define MAXT (MAXN + MAXE)

// ---------------- static device scratch -------------------------------------
__device__ __align__(16) float g_h1  [MAXN * 64];
__device__ __align__(16) float g_as1 [MAXN * 4];
__device__ __align__(16) float g_ad1 [MAXN * 4];
__device__ __align__(16) float g_agg1[MAXN * 64];
__device__ __align__(16) float g_h2  [MAXN * 40];
__device__            float g_as2 [MAXN];
__device__            float g_ad2 [MAXN];
__device__ __align__(16) float g_agg2[MAXN * 40];
// CSR structures (rebuilt every launch; dst-sorted)
__device__ int g_deg     [MAXN];
__device__ int g_rowstart[MAXN + 1];
__device__ int g_cursor  [MAXN];
__device__ int g_srcs    [MAXT];

__device__ __forceinline__ float lrelu(float v) { return v > 0.f ? v : 0.2f * v; }

// ---------------- CSR build --------------------------------------------------
__global__ void k_zero_deg(int n) {
    int i = blockIdx.x * blockDim.x + threadIdx.x;
    if (i < n) g_deg[i] = 0;
}

__global__ void k_hist(const int* __restrict__ ei, int e, int n) {
    int t = blockIdx.x * blockDim.x + threadIdx.x;
    if (t >= e + n) return;
    int dst = (t < e) ? ei[e + t] : (t - e);
    atomicAdd(&g_deg[dst], 1);
}

__global__ void k_scan(int n) {
    __shared__ int sums[1024];
    int tid = threadIdx.x;
    int per = (n + 1023) >> 10;
    int start = tid * per;
    int fin = min(start + per, n);
    int s = 0;
    for (int i = start; i < fin; i++) s += g_deg[i];
    sums[tid] = s;
    __syncthreads();
    for (int off = 1; off < 1024; off <<= 1) {
        int add = (tid >= off) ? sums[tid - off] : 0;
        __syncthreads();
        sums[tid] += add;
        __syncthreads();
    }
    int run = sums[tid] - s;   // exclusive prefix
    for (int i = start; i < fin; i++) {
        g_rowstart[i] = run;
        g_cursor[i]   = run;
        run += g_deg[i];
    }
    if (tid == 0) g_rowstart[n] = sums[1023];
}

__global__ void k_scatter(const int* __restrict__ ei, int e, int n) {
    int t = blockIdx.x * blockDim.x + threadIdx.x;
    if (t >= e + n) return;
    int src, dst;
    if (t < e) { src = ei[t]; dst = ei[e + t]; } else { src = dst = t - e; }
    int pos = atomicAdd(&g_cursor[dst], 1);
    g_srcs[pos] = src;
}

// ---------------- tiled GEMM1: h1 = x @ W1^T  (n x 128) @ (128 x 64) ---------
// K-tiled into 2 chunks of 64 to fit 48KB static smem.
#define G1_TM 64
__global__ void k_gemm1(const float* __restrict__ x, const float* __restrict__ W1, int n) {
    __shared__ float As[G1_TM * 68];   // 64 rows x 64 k, stride 68 (pad)
    __shared__ float Bs[64 * 64];      // Bs[kk*64 + c] = W1[c*128 + kt*64 + kk]
    int tid = threadIdx.x;
    int row0 = blockIdx.x * G1_TM;
    int tr = tid >> 4, tc = tid & 15;   // 16 x 16 thread grid, 4x4 outputs each

    float acc[4][4] = {};
    const float4* Bs4 = (const float4*)Bs;

    #pragma unroll
    for (int kt = 0; kt < 2; kt++) {
        // load W1 chunk transposed
        for (int i = tid; i < 64 * 64; i += 256) {
            int c = i >> 6, kk = i & 63;
            Bs[kk * 64 + c] = W1[c * 128 + kt * 64 + kk];
        }
        // load x chunk: 64 rows x 16 float4s
        for (int i = tid; i < G1_TM * 16; i += 256) {
            int r = i >> 4, k4 = i & 15;
            int row = row0 + r;
            float4 v = (row < n) ? *(const float4*)&x[(size_t)row * 128 + kt * 64 + k4 * 4]
                                 : make_float4(0.f, 0.f, 0.f, 0.f);
            *(float4*)&As[r * 68 + k4 * 4] = v;
        }
        __syncthreads();

        #pragma unroll 4
        for (int k = 0; k < 64; k++) {
            float a0 = As[(tr * 4 + 0) * 68 + k];
            float a1 = As[(tr * 4 + 1) * 68 + k];
            float a2 = As[(tr * 4 + 2) * 68 + k];
            float a3 = As[(tr * 4 + 3) * 68 + k];
            float4 b = Bs4[k * 16 + tc];
            acc[0][0] = fmaf(a0, b.x, acc[0][0]); acc[0][1] = fmaf(a0, b.y, acc[0][1]);
            acc[0][2] = fmaf(a0, b.z, acc[0][2]); acc[0][3] = fmaf(a0, b.w, acc[0][3]);
            acc[1][0] = fmaf(a1, b.x, acc[1][0]); acc[1][1] = fmaf(a1, b.y, acc[1][1]);
            acc[1][2] = fmaf(a1, b.z, acc[1][2]); acc[1][3] = fmaf(a1, b.w, acc[1][3]);
            acc[2][0] = fmaf(a2, b.x, acc[2][0]); acc[2][1] = fmaf(a2, b.y, acc[2][1]);
            acc[2][2] = fmaf(a2, b.z, acc[2][2]); acc[2][3] = fmaf(a2, b.w, acc[2][3]);
            acc[3][0] = fmaf(a3, b.x, acc[3][0]); acc[3][1] = fmaf(a3, b.y, acc[3][1]);
            acc[3][2] = fmaf(a3, b.z, acc[3][2]); acc[3][3] = fmaf(a3, b.w, acc[3][3]);
        }
        __syncthreads();
    }

    int col = tc * 4;
    #pragma unroll
    for (int i = 0; i < 4; i++) {
        int row = row0 + tr * 4 + i;
        if (row < n)
            *(float4*)&g_h1[(size_t)row * 64 + col] =
                make_float4(acc[i][0], acc[i][1], acc[i][2], acc[i][3]);
    }
}

// ---------------- alpha1: per-node attention scalars -------------------------
__global__ void k_alpha1(const float* __restrict__ a_s, const float* __restrict__ a_d, int n) {
    int lane = threadIdx.x & 31;
    int row  = (blockIdx.x * blockDim.x + threadIdx.x) >> 5;
    if (row >= n) return;
    float2 h   = *(const float2*)&g_h1[(size_t)row * 64 + lane * 2];
    float2 asv = *(const float2*)&a_s[lane * 2];
    float2 adv = *(const float2*)&a_d[lane * 2];
    float ps = h.x * asv.x + h.y * asv.y;
    float pd = h.x * adv.x + h.y * adv.y;
    #pragma unroll
    for (int off = 4; off; off >>= 1) {
        ps += __shfl_down_sync(0xffffffffu, ps, off, 8);
        pd += __shfl_down_sync(0xffffffffu, pd, off, 8);
    }
    if ((lane & 7) == 0) {
        int head = lane >> 3;
        g_as1[row * 4 + head] = ps;
        g_ad1[row * 4 + head] = pd;
    }
}

// ---------------- layer1 fused softmax + aggregate (warp per dst) ------------
__global__ void k_agg1(int n) {
    __shared__ __align__(16) float es[8][128];
    __shared__ int ss[8][32];
    int w = threadIdx.x >> 5, lane = threadIdx.x & 31;
    int dst = blockIdx.x * 8 + w;
    if (dst >= n) return;
    int row = g_rowstart[dst], end = g_rowstart[dst + 1];
    float4 ad = *(const float4*)&g_ad1[dst * 4];
    int head = lane >> 3;
    float2 acc = make_float2(0.f, 0.f);
    float4 den = make_float4(0.f, 0.f, 0.f, 0.f);

    for (int base = row; base < end; base += 32) {
        int k = base + lane;
        float4 e4 = make_float4(0.f, 0.f, 0.f, 0.f);
        int s = 0;
        if (k < end) {
            s = g_srcs[k];
            float4 as = *(const float4*)&g_as1[s * 4];
            e4.x = __expf(lrelu(as.x + ad.x));
            e4.y = __expf(lrelu(as.y + ad.y));
            e4.z = __expf(lrelu(as.z + ad.z));
            e4.w = __expf(lrelu(as.w + ad.w));
            den.x += e4.x; den.y += e4.y; den.z += e4.z; den.w += e4.w;
        }
        ss[w][lane] = s;
        *(float4*)&es[w][lane * 4] = e4;
        __syncwarp();
        int m = min(32, end - base);
        #pragma unroll 4
        for (int k2 = 0; k2 < m; k2++) {
            int s2   = ss[w][k2];
            float ek = es[w][k2 * 4 + head];
            float2 h = *(const float2*)&g_h1[(size_t)s2 * 64 + lane * 2];
            acc.x = fmaf(ek, h.x, acc.x);
            acc.y = fmaf(ek, h.y, acc.y);
        }
        __syncwarp();
    }
    #pragma unroll
    for (int off = 16; off; off >>= 1) {
        den.x += __shfl_xor_sync(0xffffffffu, den.x, off);
        den.y += __shfl_xor_sync(0xffffffffu, den.y, off);
        den.z += __shfl_xor_sync(0xffffffffu, den.z, off);
        den.w += __shfl_xor_sync(0xffffffffu, den.w, off);
    }
    float d   = head == 0 ? den.x : head == 1 ? den.y : head == 2 ? den.z : den.w;
    float inv = __frcp_rn(d);
    *(float2*)&g_agg1[(size_t)dst * 64 + lane * 2] = make_float2(acc.x * inv, acc.y * inv);
}

// ---------------- gemm2: relu(agg1+b1) @ W2^T + alpha2 (warp per row) --------
__global__ void k_gemm2(const float* __restrict__ b1, const float* __restrict__ W2,
                        const float* __restrict__ a_s, const float* __restrict__ a_d,
                        int n) {
    __shared__ float Wt[64 * 40];
    __shared__ float sa[40], sd[40];
    int tid = threadIdx.x;
    for (int i = tid; i < 40 * 64; i += blockDim.x) {
        int c = i / 64, k = i - c * 64;
        Wt[k * 40 + c] = W2[i];
    }
    if (tid < 40) { sa[tid] = a_s[tid]; sd[tid] = a_d[tid]; }
    __syncthreads();

    int lane   = tid & 31;
    int warp   = (blockIdx.x * blockDim.x + tid) >> 5;
    int nwarps = (gridDim.x * blockDim.x) >> 5;

    for (int row = warp; row < n; row += nwarps) {
        float v0 = fmaxf(g_agg1[(size_t)row * 64 + lane]      + b1[lane],      0.f);
        float v1 = fmaxf(g_agg1[(size_t)row * 64 + lane + 32] + b1[lane + 32], 0.f);
        float acc0 = 0.f, acc1 = 0.f;
        #pragma unroll
        for (int k = 0; k < 64; k++) {
            float xk = (k < 32) ? __shfl_sync(0xffffffffu, v0, k)
                                : __shfl_sync(0xffffffffu, v1, k - 32);
            acc0 = fmaf(Wt[k * 40 + lane], xk, acc0);
            if (lane < 8) acc1 = fmaf(Wt[k * 40 + lane + 32], xk, acc1);
        }
        g_h2[(size_t)row * 40 + lane] = acc0;
        if (lane < 8) g_h2[(size_t)row * 40 + 32 + lane] = acc1;

        float ps = acc0 * sa[lane] + (lane < 8 ? acc1 * sa[lane + 32] : 0.f);
        float pd = acc0 * sd[lane] + (lane < 8 ? acc1 * sd[lane + 32] : 0.f);
        #pragma unroll
        for (int off = 16; off; off >>= 1) {
            ps += __shfl_xor_sync(0xffffffffu, ps, off);
            pd += __shfl_xor_sync(0xffffffffu, pd, off);
        }
        if (lane == 0) { g_as2[row] = ps; g_ad2[row] = pd; }
    }
}

// ---------------- layer2 fused softmax + aggregate (warp per dst) ------------
__global__ void k_agg2(int n) {
    __shared__ float es[8][32];
    __shared__ int   ss[8][32];
    int w = threadIdx.x >> 5, lane = threadIdx.x & 31;
    int dst = blockIdx.x * 8 + w;
    if (dst >= n) return;
    int row = g_rowstart[dst], end = g_rowstart[dst + 1];
    float ad = g_ad2[dst];
    float acc0 = 0.f, acc1 = 0.f, den = 0.f;

    for (int base = row; base < end; base += 32) {
        int k = base + lane;
        float e = 0.f;
        int s = 0;
        if (k < end) {
            s = g_srcs[k];
            e = __expf(lrelu(g_as2[s] + ad));
            den += e;
        }
        ss[w][lane] = s;
        es[w][lane] = e;
        __syncwarp();
        int m = min(32, end - base);
        #pragma unroll 4
        for (int k2 = 0; k2 < m; k2++) {
            int s2   = ss[w][k2];
            float ek = es[w][k2];
            acc0 = fmaf(ek, g_h2[(size_t)s2 * 40 + lane], acc0);
            if (lane < 8) acc1 = fmaf(ek, g_h2[(size_t)s2 * 40 + 32 + lane], acc1);
        }
        __syncwarp();
    }
    #pragma unroll
    for (int off = 16; off; off >>= 1) den += __shfl_xor_sync(0xffffffffu, den, off);
    float inv = __frcp_rn(den);
    g_agg2[(size_t)dst * 40 + lane] = acc0 * inv;
    if (lane < 8) g_agg2[(size_t)dst * 40 + 32 + lane] = acc1 * inv;
}

// ---------------- bias + log_softmax -> out ----------------------------------
__global__ void k_final(const float* __restrict__ b2, float* __restrict__ out, int n) {
    int lane = threadIdx.x & 31;
    int row  = (blockIdx.x * blockDim.x + threadIdx.x) >> 5;
    if (row >= n) return;
    float v0 = g_agg2[(size_t)row * 40 + lane] + b2[lane];
    float v1 = (lane < 8) ? (g_agg2[(size_t)row * 40 + 32 + lane] + b2[32 + lane]) : -1e30f;
    float m = fmaxf(v0, v1);
    #pragma unroll
    for (int off = 16; off; off >>= 1) m = fmaxf(m, __shfl_xor_sync(0xffffffffu, m, off));
    float s = __expf(v0 - m) + (lane < 8 ? __expf(v1 - m) : 0.f);
    #pragma unroll
    for (int off = 16; off; off >>= 1) s += __shfl_xor_sync(0xffffffffu, s, off);
    float ls = m + logf(s);
    out[(size_t)row * 40 + lane] = v0 - ls;
    if (lane < 8) out[(size_t)row * 40 + 32 + lane] = v1 - ls;
}

// ---------------- launcher ---------------------------------------------------
extern "C" void kernel_launch(void* const* d_in, const int* in_sizes, int n_in,
                              void* d_out, int out_size) {
    const float* x      = (const float*)d_in[0];
    const int*   ei     = (const int*)  d_in[1];
    const float* W1     = (const float*)d_in[2];
    const float* a_src1 = (const float*)d_in[3];
    const float* a_dst1 = (const float*)d_in[4];
    const float* b1     = (const float*)d_in[5];
    const float* W2     = (const float*)d_in[6];
    const float* a_src2 = (const float*)d_in[7];
    const float* a_dst2 = (const float*)d_in[8];
    const float* b2     = (const float*)d_in[9];
    float* out = (float*)d_out;

    int n = in_sizes[0] / 128;
    int e = in_sizes[1] / 2;
    int T = e + n;

    // CSR build (dst-sorted)
    k_zero_deg<<<(n + 255) / 256, 256>>>(n);
    k_hist    <<<(T + 255) / 256, 256>>>(ei, e, n);
    k_scan    <<<1, 1024>>>(n);
    k_scatter <<<(T + 255) / 256, 256>>>(ei, e, n);
    // layer 1
    k_gemm1   <<<(n + G1_TM - 1) / G1_TM, 256>>>(x, W1, n);
    k_alpha1  <<<(n * 32 + 255) / 256, 256>>>(a_src1, a_dst1, n);
    k_agg1    <<<(n + 7) / 8, 256>>>(n);
    // layer 2
    k_gemm2   <<<1024, 256>>>(b1, W2, a_src2, a_dst2, n);
    k_agg2    <<<(n + 7) / 8, 256>>>(n);
    k_final   <<<(n * 32 + 255) / 256, 256>>>(b2, out, n);
}

// round 5
// speedup vs baseline: 1.5808x; 1.5329x over previous
#include <cuda_runtime.h>
#include <math.h>

#define MAXN 100000
#define MAXE 1600000
#define MAXT (MAXN + MAXE)
#define NB_MAX 1024

// ---------------- static device scratch -------------------------------------
__device__ __align__(16) float g_h1  [MAXN * 64];
__device__ __align__(16) float g_as1 [MAXN * 4];
__device__ __align__(16) float g_ad1 [MAXN * 4];
__device__ __align__(16) float g_h2  [MAXN * 40];
__device__            float g_as2 [MAXN];
__device__            float g_ad2 [MAXN];
// CSR structures (rebuilt every launch; dst-sorted). Padded so int4/scan code
// never needs bounds checks: pad region is never written and stays zero.
__device__ int g_deg     [MAXN + 1024];
__device__ int g_rowstart[MAXN + 1024];
__device__ int g_cursor  [MAXN + 1024];
__device__ int g_srcs    [MAXT];
__device__ int g_bsum[NB_MAX];
__device__ int g_boff[NB_MAX];

__device__ __forceinline__ float lrelu(float v) { return v > 0.f ? v : 0.2f * v; }

// ---------------- CSR build --------------------------------------------------
__global__ void k_zero_deg(int n) {
    int i = blockIdx.x * blockDim.x + threadIdx.x;
    if (i < n) g_deg[i] = 0;
}

__global__ void k_hist(const int* __restrict__ ei, int e, int n) {
    int t = blockIdx.x * blockDim.x + threadIdx.x;
    if (t >= e + n) return;
    int dst = (t < e) ? __ldg(&ei[e + t]) : (t - e);
    atomicAdd(&g_deg[dst], 1);
}

// per-1024-chunk sums (256 threads, int4 loads)
__global__ void k_blocksum() {
    __shared__ int wsum[8];
    int b = blockIdx.x, tid = threadIdx.x;
    int4 d = *(const int4*)&g_deg[b * 1024 + tid * 4];
    int s = d.x + d.y + d.z + d.w;
    #pragma unroll
    for (int off = 16; off; off >>= 1) s += __shfl_down_sync(0xffffffffu, s, off);
    if ((tid & 31) == 0) wsum[tid >> 5] = s;
    __syncthreads();
    if (tid == 0) {
        int t = 0;
        #pragma unroll
        for (int i = 0; i < 8; i++) t += wsum[i];
        g_bsum[b] = t;
    }
}

// single-block scan over block sums (nb <= 1024)
__global__ void k_scanb(int nb, int n) {
    __shared__ int sm[1024];
    int tid = threadIdx.x;
    int v = (tid < nb) ? g_bsum[tid] : 0;
    sm[tid] = v;
    __syncthreads();
    for (int off = 1; off < 1024; off <<= 1) {
        int a = (tid >= off) ? sm[tid - off] : 0;
        __syncthreads();
        sm[tid] += a;
        __syncthreads();
    }
    if (tid < nb) g_boff[tid] = sm[tid] - v;   // exclusive block offset
    if (tid == 1023) g_rowstart[n] = sm[1023]; // total
}

// per-element exclusive prefix within each 1024-chunk + block offset
__global__ void k_writerow() {
    __shared__ int tsum[256];
    int b = blockIdx.x, tid = threadIdx.x;
    int idx = b * 1024 + tid * 4;
    int4 d = *(const int4*)&g_deg[idx];
    int s = d.x + d.y + d.z + d.w;
    tsum[tid] = s;
    __syncthreads();
    for (int off = 1; off < 256; off <<= 1) {
        int a = (tid >= off) ? tsum[tid - off] : 0;
        __syncthreads();
        tsum[tid] += a;
        __syncthreads();
    }
    int r = tsum[tid] - s + g_boff[b];
    g_rowstart[idx] = r;     g_cursor[idx] = r;     r += d.x;
    g_rowstart[idx + 1] = r; g_cursor[idx + 1] = r; r += d.y;
    g_rowstart[idx + 2] = r; g_cursor[idx + 2] = r; r += d.z;
    g_rowstart[idx + 3] = r; g_cursor[idx + 3] = r;
}

__global__ void k_scatter(const int* __restrict__ ei, int e, int n) {
    int t = blockIdx.x * blockDim.x + threadIdx.x;
    if (t >= e + n) return;
    int src, dst;
    if (t < e) { src = __ldg(&ei[t]); dst = __ldg(&ei[e + t]); } else { src = dst = t - e; }
    int pos = atomicAdd(&g_cursor[dst], 1);
    g_srcs[pos] = src;
}

// ---------------- tiled GEMM1: h1 = x @ W1^T  (n x 128) @ (128 x 64) ---------
#define G1_TM 64
__global__ void k_gemm1(const float* __restrict__ x, const float* __restrict__ W1, int n) {
    __shared__ float As[G1_TM * 68];
    __shared__ float Bs[64 * 64];
    int tid = threadIdx.x;
    int row0 = blockIdx.x * G1_TM;
    int tr = tid >> 4, tc = tid & 15;

    float acc[4][4] = {};
    const float4* Bs4 = (const float4*)Bs;

    #pragma unroll
    for (int kt = 0; kt < 2; kt++) {
        for (int i = tid; i < 64 * 64; i += 256) {
            int c = i >> 6, kk = i & 63;
            Bs[kk * 64 + c] = W1[c * 128 + kt * 64 + kk];
        }
        for (int i = tid; i < G1_TM * 16; i += 256) {
            int r = i >> 4, k4 = i & 15;
            int row = row0 + r;
            float4 v = (row < n) ? *(const float4*)&x[(size_t)row * 128 + kt * 64 + k4 * 4]
                                 : make_float4(0.f, 0.f, 0.f, 0.f);
            *(float4*)&As[r * 68 + k4 * 4] = v;
        }
        __syncthreads();

        #pragma unroll 4
        for (int k = 0; k < 64; k++) {
            float a0 = As[(tr * 4 + 0) * 68 + k];
            float a1 = As[(tr * 4 + 1) * 68 + k];
            float a2 = As[(tr * 4 + 2) * 68 + k];
            float a3 = As[(tr * 4 + 3) * 68 + k];
            float4 b = Bs4[k * 16 + tc];
            acc[0][0] = fmaf(a0, b.x, acc[0][0]); acc[0][1] = fmaf(a0, b.y, acc[0][1]);
            acc[0][2] = fmaf(a0, b.z, acc[0][2]); acc[0][3] = fmaf(a0, b.w, acc[0][3]);
            acc[1][0] = fmaf(a1, b.x, acc[1][0]); acc[1][1] = fmaf(a1, b.y, acc[1][1]);
            acc[1][2] = fmaf(a1, b.z, acc[1][2]); acc[1][3] = fmaf(a1, b.w, acc[1][3]);
            acc[2][0] = fmaf(a2, b.x, acc[2][0]); acc[2][1] = fmaf(a2, b.y, acc[2][1]);
            acc[2][2] = fmaf(a2, b.z, acc[2][2]); acc[2][3] = fmaf(a2, b.w, acc[2][3]);
            acc[3][0] = fmaf(a3, b.x, acc[3][0]); acc[3][1] = fmaf(a3, b.y, acc[3][1]);
            acc[3][2] = fmaf(a3, b.z, acc[3][2]); acc[3][3] = fmaf(a3, b.w, acc[3][3]);
        }
        __syncthreads();
    }

    int col = tc * 4;
    #pragma unroll
    for (int i = 0; i < 4; i++) {
        int row = row0 + tr * 4 + i;
        if (row < n)
            *(float4*)&g_h1[(size_t)row * 64 + col] =
                make_float4(acc[i][0], acc[i][1], acc[i][2], acc[i][3]);
    }
}

// ---------------- alpha1 ------------------------------------------------------
__global__ void k_alpha1(const float* __restrict__ a_s, const float* __restrict__ a_d, int n) {
    int lane = threadIdx.x & 31;
    int row  = (blockIdx.x * blockDim.x + threadIdx.x) >> 5;
    if (row >= n) return;
    float2 h   = *(const float2*)&g_h1[(size_t)row * 64 + lane * 2];
    float2 asv = *(const float2*)&a_s[lane * 2];
    float2 adv = *(const float2*)&a_d[lane * 2];
    float ps = h.x * asv.x + h.y * asv.y;
    float pd = h.x * adv.x + h.y * adv.y;
    #pragma unroll
    for (int off = 4; off; off >>= 1) {
        ps += __shfl_down_sync(0xffffffffu, ps, off, 8);
        pd += __shfl_down_sync(0xffffffffu, pd, off, 8);
    }
    if ((lane & 7) == 0) {
        int head = lane >> 3;
        g_as1[row * 4 + head] = ps;
        g_ad1[row * 4 + head] = pd;
    }
}

// ------ layer1 fused: softmax-aggregate + relu+bias + gemm2 + alpha2 ---------
// Warp per dst, grid-stride over dst groups. W2 tile loaded once per block.
__global__ void k_agg1f(const float* __restrict__ b1, const float* __restrict__ W2,
                        const float* __restrict__ a_s2, const float* __restrict__ a_d2,
                        int n) {
    __shared__ float Wt[64 * 40];   // Wt[k*40+c] = W2[c*64+k]
    __shared__ float sa[40], sd[40], b1s[64];
    __shared__ __align__(16) float es[8][128];
    __shared__ int ss[8][32];
    int tid = threadIdx.x;
    for (int i = tid; i < 40 * 64; i += 256) {
        int c = i / 64, k = i - c * 64;
        Wt[k * 40 + c] = W2[i];
    }
    if (tid < 40) { sa[tid] = a_s2[tid]; sd[tid] = a_d2[tid]; }
    if (tid < 64) b1s[tid] = b1[tid];
    __syncthreads();

    int w = tid >> 5, lane = tid & 31;
    int head = lane >> 3;
    int ngroups = gridDim.x * 8;

    for (int dst = blockIdx.x * 8 + w; dst < n; dst += ngroups) {
        int row = g_rowstart[dst], end = g_rowstart[dst + 1];
        float4 ad = *(const float4*)&g_ad1[dst * 4];
        float2 acc = make_float2(0.f, 0.f);
        float4 den = make_float4(0.f, 0.f, 0.f, 0.f);

        for (int base = row; base < end; base += 32) {
            int k = base + lane;
            float4 e4 = make_float4(0.f, 0.f, 0.f, 0.f);
            int s = 0;
            if (k < end) {
                s = g_srcs[k];
                float4 as = *(const float4*)&g_as1[s * 4];
                e4.x = __expf(lrelu(as.x + ad.x));
                e4.y = __expf(lrelu(as.y + ad.y));
                e4.z = __expf(lrelu(as.z + ad.z));
                e4.w = __expf(lrelu(as.w + ad.w));
                den.x += e4.x; den.y += e4.y; den.z += e4.z; den.w += e4.w;
            }
            ss[w][lane] = s;
            *(float4*)&es[w][lane * 4] = e4;
            __syncwarp();
            int m = min(32, end - base);
            #pragma unroll 4
            for (int k2 = 0; k2 < m; k2++) {
                int s2   = ss[w][k2];
                float ek = es[w][k2 * 4 + head];
                float2 h = *(const float2*)&g_h1[(size_t)s2 * 64 + lane * 2];
                acc.x = fmaf(ek, h.x, acc.x);
                acc.y = fmaf(ek, h.y, acc.y);
            }
            __syncwarp();
        }
        #pragma unroll
        for (int off = 16; off; off >>= 1) {
            den.x += __shfl_xor_sync(0xffffffffu, den.x, off);
            den.y += __shfl_xor_sync(0xffffffffu, den.y, off);
            den.z += __shfl_xor_sync(0xffffffffu, den.z, off);
            den.w += __shfl_xor_sync(0xffffffffu, den.w, off);
        }
        float d   = head == 0 ? den.x : head == 1 ? den.y : head == 2 ? den.z : den.w;
        float inv = __frcp_rn(d);
        // relu(agg + b1): lane holds channels 2*lane, 2*lane+1
        float vx = fmaxf(acc.x * inv + b1s[2 * lane],     0.f);
        float vy = fmaxf(acc.y * inv + b1s[2 * lane + 1], 0.f);
        // gemm2: h2[c] = sum_k v[k] * Wt[k*40+c]
        float o0 = 0.f, o1 = 0.f;
        #pragma unroll
        for (int k = 0; k < 64; k++) {
            float xk = __shfl_sync(0xffffffffu, (k & 1) ? vy : vx, k >> 1);
            o0 = fmaf(Wt[k * 40 + lane], xk, o0);
            if (lane < 8) o1 = fmaf(Wt[k * 40 + 32 + lane], xk, o1);
        }
        g_h2[(size_t)dst * 40 + lane] = o0;
        if (lane < 8) g_h2[(size_t)dst * 40 + 32 + lane] = o1;
        // alpha2
        float ps = o0 * sa[lane] + (lane < 8 ? o1 * sa[32 + lane] : 0.f);
        float pd = o0 * sd[lane] + (lane < 8 ? o1 * sd[32 + lane] : 0.f);
        #pragma unroll
        for (int off = 16; off; off >>= 1) {
            ps += __shfl_xor_sync(0xffffffffu, ps, off);
            pd += __shfl_xor_sync(0xffffffffu, pd, off);
        }
        if (lane == 0) { g_as2[dst] = ps; g_ad2[dst] = pd; }
    }
}

// ------ layer2 fused: softmax-aggregate + bias + log_softmax -> out ----------
__global__ void k_agg2f(const float* __restrict__ b2, float* __restrict__ out, int n) {
    __shared__ float es[8][32];
    __shared__ int   ss[8][32];
    int tid = threadIdx.x;
    int w = tid >> 5, lane = tid & 31;
    int ngroups = gridDim.x * 8;

    float b2a = __ldg(&b2[lane]);
    float b2b = (lane < 8) ? __ldg(&b2[32 + lane]) : 0.f;

    for (int dst = blockIdx.x * 8 + w; dst < n; dst += ngroups) {
        int row = g_rowstart[dst], end = g_rowstart[dst + 1];
        float ad = g_ad2[dst];
        float acc0 = 0.f, acc1 = 0.f, den = 0.f;

        for (int base = row; base < end; base += 32) {
            int k = base + lane;
            float e = 0.f;
            int s = 0;
            if (k < end) {
                s = g_srcs[k];
                e = __expf(lrelu(g_as2[s] + ad));
                den += e;
            }
            ss[w][lane] = s;
            es[w][lane] = e;
            __syncwarp();
            int m = min(32, end - base);
            #pragma unroll 4
            for (int k2 = 0; k2 < m; k2++) {
                int s2   = ss[w][k2];
                float ek = es[w][k2];
                acc0 = fmaf(ek, g_h2[(size_t)s2 * 40 + lane], acc0);
                if (lane < 8) acc1 = fmaf(ek, g_h2[(size_t)s2 * 40 + 32 + lane], acc1);
            }
            __syncwarp();
        }
        #pragma unroll
        for (int off = 16; off; off >>= 1) den += __shfl_xor_sync(0xffffffffu, den, off);
        float inv = __frcp_rn(den);
        // bias + log_softmax over 40 classes
        float v0 = acc0 * inv + b2a;
        float v1 = (lane < 8) ? (acc1 * inv + b2b) : -1e30f;
        float m = fmaxf(v0, v1);
        #pragma unroll
        for (int off = 16; off; off >>= 1) m = fmaxf(m, __shfl_xor_sync(0xffffffffu, m, off));
        float s = __expf(v0 - m) + (lane < 8 ? __expf(v1 - m) : 0.f);
        #pragma unroll
        for (int off = 16; off; off >>= 1) s += __shfl_xor_sync(0xffffffffu, s, off);
        float ls = m + logf(s);
        out[(size_t)dst * 40 + lane] = v0 - ls;
        if (lane < 8) out[(size_t)dst * 40 + 32 + lane] = v1 - ls;
    }
}

// ---------------- launcher ---------------------------------------------------
extern "C" void kernel_launch(void* const* d_in, const int* in_sizes, int n_in,
                              void* d_out, int out_size) {
    const float* x      = (const float*)d_in[0];
    const int*   ei     = (const int*)  d_in[1];
    const float* W1     = (const float*)d_in[2];
    const float* a_src1 = (const float*)d_in[3];
    const float* a_dst1 = (const float*)d_in[4];
    const float* b1     = (const float*)d_in[5];
    const float* W2     = (const float*)d_in[6];
    const float* a_src2 = (const float*)d_in[7];
    const float* a_dst2 = (const float*)d_in[8];
    const float* b2     = (const float*)d_in[9];
    float* out = (float*)d_out;

    int n = in_sizes[0] / 128;
    int e = in_sizes[1] / 2;
    int T = e + n;
    int nb = (n + 1023) >> 10;

    // CSR build (dst-sorted), parallel scan
    k_zero_deg <<<(n + 255) / 256, 256>>>(n);
    k_hist     <<<(T + 255) / 256, 256>>>(ei, e, n);
    k_blocksum <<<nb, 256>>>();
    k_scanb    <<<1, 1024>>>(nb, n);
    k_writerow <<<nb, 256>>>();
    k_scatter  <<<(T + 255) / 256, 256>>>(ei, e, n);
    // layer 1
    k_gemm1    <<<(n + G1_TM - 1) / G1_TM, 256>>>(x, W1, n);
    k_alpha1   <<<(n * 32 + 255) / 256, 256>>>(a_src1, a_dst1, n);
    k_agg1f    <<<1184, 256>>>(b1, W2, a_src2, a_dst2, n);
    // layer 2 (fused log-softmax)
    k_agg2f    <<<1184, 256>>>(b2, out, n);
}

// round 6
// speedup vs baseline: 1.5835x; 1.0017x over previous
#include <cuda_runtime.h>
#include <math.h>

#define MAXN 100000
#define MAXE 1600000
#define MAXT (MAXN + MAXE)
#define NB_MAX 1024

// ---------------- static device scratch -------------------------------------
__device__ __align__(16) float g_h1  [MAXN * 64];
__device__ __align__(16) float g_as1 [MAXN * 4];
__device__ __align__(16) float g_ad1 [MAXN * 4];
__device__ __align__(16) float g_h2  [MAXN * 40];
__device__            float g_as2 [MAXN];
__device__            float g_ad2 [MAXN];
// CSR structures (rebuilt every launch; dst-sorted). Padded so int4/scan code
// never needs bounds checks: pad region is never written and stays zero.
__device__ int g_deg     [MAXN + 1024];
__device__ int g_rowstart[MAXN + 1024];
__device__ int g_cursor  [MAXN + 1024];
__device__ int g_srcs    [MAXT];
__device__ int g_bsum[NB_MAX];
__device__ int g_boff[NB_MAX];

__device__ __forceinline__ float lrelu(float v) { return v > 0.f ? v : 0.2f * v; }

// ---------------- CSR build --------------------------------------------------
__global__ void k_zero_deg(int n) {
    int i = blockIdx.x * blockDim.x + threadIdx.x;
    if (i < n) g_deg[i] = 0;
}

__global__ void k_hist(const int* __restrict__ ei, int e, int n) {
    int t = blockIdx.x * blockDim.x + threadIdx.x;
    if (t >= e + n) return;
    int dst = (t < e) ? __ldg(&ei[e + t]) : (t - e);
    atomicAdd(&g_deg[dst], 1);
}

// per-1024-chunk sums (256 threads, int4 loads)
__global__ void k_blocksum() {
    __shared__ int wsum[8];
    int b = blockIdx.x, tid = threadIdx.x;
    int4 d = *(const int4*)&g_deg[b * 1024 + tid * 4];
    int s = d.x + d.y + d.z + d.w;
    #pragma unroll
    for (int off = 16; off; off >>= 1) s += __shfl_down_sync(0xffffffffu, s, off);
    if ((tid & 31) == 0) wsum[tid >> 5] = s;
    __syncthreads();
    if (tid == 0) {
        int t = 0;
        #pragma unroll
        for (int i = 0; i < 8; i++) t += wsum[i];
        g_bsum[b] = t;
    }
}

// single-block scan over block sums (nb <= 1024)
__global__ void k_scanb(int nb, int n) {
    __shared__ int sm[1024];
    int tid = threadIdx.x;
    int v = (tid < nb) ? g_bsum[tid] : 0;
    sm[tid] = v;
    __syncthreads();
    for (int off = 1; off < 1024; off <<= 1) {
        int a = (tid >= off) ? sm[tid - off] : 0;
        __syncthreads();
        sm[tid] += a;
        __syncthreads();
    }
    if (tid < nb) g_boff[tid] = sm[tid] - v;   // exclusive block offset
    if (tid == 1023) g_rowstart[n] = sm[1023]; // total
}

// per-element exclusive prefix within each 1024-chunk + block offset
__global__ void k_writerow() {
    __shared__ int tsum[256];
    int b = blockIdx.x, tid = threadIdx.x;
    int idx = b * 1024 + tid * 4;
    int4 d = *(const int4*)&g_deg[idx];
    int s = d.x + d.y + d.z + d.w;
    tsum[tid] = s;
    __syncthreads();
    for (int off = 1; off < 256; off <<= 1) {
        int a = (tid >= off) ? tsum[tid - off] : 0;
        __syncthreads();
        tsum[tid] += a;
        __syncthreads();
    }
    int r = tsum[tid] - s + g_boff[b];
    g_rowstart[idx] = r;     g_cursor[idx] = r;     r += d.x;
    g_rowstart[idx + 1] = r; g_cursor[idx + 1] = r; r += d.y;
    g_rowstart[idx + 2] = r; g_cursor[idx + 2] = r; r += d.z;
    g_rowstart[idx + 3] = r; g_cursor[idx + 3] = r;
}

__global__ void k_scatter(const int* __restrict__ ei, int e, int n) {
    int t = blockIdx.x * blockDim.x + threadIdx.x;
    if (t >= e + n) return;
    int src, dst;
    if (t < e) { src = __ldg(&ei[t]); dst = __ldg(&ei[e + t]); } else { src = dst = t - e; }
    int pos = atomicAdd(&g_cursor[dst], 1);
    g_srcs[pos] = src;
}

// ---------------- tiled GEMM1: h1 = x @ W1^T  (n x 128) @ (128 x 64) ---------
#define G1_TM 64
__global__ void k_gemm1(const float* __restrict__ x, const float* __restrict__ W1, int n) {
    __shared__ float As[G1_TM * 68];
    __shared__ float Bs[64 * 64];
    int tid = threadIdx.x;
    int row0 = blockIdx.x * G1_TM;
    int tr = tid >> 4, tc = tid & 15;

    float acc[4][4] = {};
    const float4* Bs4 = (const float4*)Bs;

    #pragma unroll
    for (int kt = 0; kt < 2; kt++) {
        for (int i = tid; i < 64 * 64; i += 256) {
            int c = i >> 6, kk = i & 63;
            Bs[kk * 64 + c] = W1[c * 128 + kt * 64 + kk];
        }
        for (int i = tid; i < G1_TM * 16; i += 256) {
            int r = i >> 4, k4 = i & 15;
            int row = row0 + r;
            float4 v = (row < n) ? *(const float4*)&x[(size_t)row * 128 + kt * 64 + k4 * 4]
                                 : make_float4(0.f, 0.f, 0.f, 0.f);
            *(float4*)&As[r * 68 + k4 * 4] = v;
        }
        __syncthreads();

        #pragma unroll 4
        for (int k = 0; k < 64; k++) {
            float a0 = As[(tr * 4 + 0) * 68 + k];
            float a1 = As[(tr * 4 + 1) * 68 + k];
            float a2 = As[(tr * 4 + 2) * 68 + k];
            float a3 = As[(tr * 4 + 3) * 68 + k];
            float4 b = Bs4[k * 16 + tc];
            acc[0][0] = fmaf(a0, b.x, acc[0][0]); acc[0][1] = fmaf(a0, b.y, acc[0][1]);
            acc[0][2] = fmaf(a0, b.z, acc[0][2]); acc[0][3] = fmaf(a0, b.w, acc[0][3]);
            acc[1][0] = fmaf(a1, b.x, acc[1][0]); acc[1][1] = fmaf(a1, b.y, acc[1][1]);
            acc[1][2] = fmaf(a1, b.z, acc[1][2]); acc[1][3] = fmaf(a1, b.w, acc[1][3]);
            acc[2][0] = fmaf(a2, b.x, acc[2][0]); acc[2][1] = fmaf(a2, b.y, acc[2][1]);
            acc[2][2] = fmaf(a2, b.z, acc[2][2]); acc[2][3] = fmaf(a2, b.w, acc[2][3]);
            acc[3][0] = fmaf(a3, b.x, acc[3][0]); acc[3][1] = fmaf(a3, b.y, acc[3][1]);
            acc[3][2] = fmaf(a3, b.z, acc[3][2]); acc[3][3] = fmaf(a3, b.w, acc[3][3]);
        }
        __syncthreads();
    }

    int col = tc * 4;
    #pragma unroll
    for (int i = 0; i < 4; i++) {
        int row = row0 + tr * 4 + i;
        if (row < n)
            *(float4*)&g_h1[(size_t)row * 64 + col] =
                make_float4(acc[i][0], acc[i][1], acc[i][2], acc[i][3]);
    }
}

// ---------------- alpha1 ------------------------------------------------------
__global__ void k_alpha1(const float* __restrict__ a_s, const float* __restrict__ a_d, int n) {
    int lane = threadIdx.x & 31;
    int row  = (blockIdx.x * blockDim.x + threadIdx.x) >> 5;
    if (row >= n) return;
    float2 h   = *(const float2*)&g_h1[(size_t)row * 64 + lane * 2];
    float2 asv = *(const float2*)&a_s[lane * 2];
    float2 adv = *(const float2*)&a_d[lane * 2];
    float ps = h.x * asv.x + h.y * asv.y;
    float pd = h.x * adv.x + h.y * adv.y;
    #pragma unroll
    for (int off = 4; off; off >>= 1) {
        ps += __shfl_down_sync(0xffffffffu, ps, off, 8);
        pd += __shfl_down_sync(0xffffffffu, pd, off, 8);
    }
    if ((lane & 7) == 0) {
        int head = lane >> 3;
        g_as1[row * 4 + head] = ps;
        g_ad1[row * 4 + head] = pd;
    }
}

// ------ layer1 fused: softmax-aggregate + relu+bias + gemm2 + alpha2 ---------
// Warp per dst, grid-stride over dst groups. W2 tile loaded once per block.
__global__ void k_agg1f(const float* __restrict__ b1, const float* __restrict__ W2,
                        const float* __restrict__ a_s2, const float* __restrict__ a_d2,
                        int n) {
    __shared__ float Wt[64 * 40];   // Wt[k*40+c] = W2[c*64+k]
    __shared__ float sa[40], sd[40], b1s[64];
    __shared__ __align__(16) float es[8][128];
    __shared__ int ss[8][32];
    int tid = threadIdx.x;
    for (int i = tid; i < 40 * 64; i += 256) {
        int c = i / 64, k = i - c * 64;
        Wt[k * 40 + c] = W2[i];
    }
    if (tid < 40) { sa[tid] = a_s2[tid]; sd[tid] = a_d2[tid]; }
    if (tid < 64) b1s[tid] = b1[tid];
    __syncthreads();

    int w = tid >> 5, lane = tid & 31;
    int head = lane >> 3;
    int ngroups = gridDim.x * 8;

    for (int dst = blockIdx.x * 8 + w; dst < n; dst += ngroups) {
        int row = g_rowstart[dst], end = g_rowstart[dst + 1];
        float4 ad = *(const float4*)&g_ad1[dst * 4];
        float2 acc = make_float2(0.f, 0.f);
        float4 den = make_float4(0.f, 0.f, 0.f, 0.f);

        for (int base = row; base < end; base += 32) {
            int k = base + lane;
            float4 e4 = make_float4(0.f, 0.f, 0.f, 0.f);
            int s = 0;
            if (k < end) {
                s = g_srcs[k];
                float4 as = *(const float4*)&g_as1[s * 4];
                e4.x = __expf(lrelu(as.x + ad.x));
                e4.y = __expf(lrelu(as.y + ad.y));
                e4.z = __expf(lrelu(as.z + ad.z));
                e4.w = __expf(lrelu(as.w + ad.w));
                den.x += e4.x; den.y += e4.y; den.z += e4.z; den.w += e4.w;
            }
            ss[w][lane] = s;
            *(float4*)&es[w][lane * 4] = e4;
            __syncwarp();
            int m = min(32, end - base);
            #pragma unroll 4
            for (int k2 = 0; k2 < m; k2++) {
                int s2   = ss[w][k2];
                float ek = es[w][k2 * 4 + head];
                float2 h = *(const float2*)&g_h1[(size_t)s2 * 64 + lane * 2];
                acc.x = fmaf(ek, h.x, acc.x);
                acc.y = fmaf(ek, h.y, acc.y);
            }
            __syncwarp();
        }
        #pragma unroll
        for (int off = 16; off; off >>= 1) {
            den.x += __shfl_xor_sync(0xffffffffu, den.x, off);
            den.y += __shfl_xor_sync(0xffffffffu, den.y, off);
            den.z += __shfl_xor_sync(0xffffffffu, den.z, off);
            den.w += __shfl_xor_sync(0xffffffffu, den.w, off);
        }
        float d   = head == 0 ? den.x : head == 1 ? den.y : head == 2 ? den.z : den.w;
        float inv = __frcp_rn(d);
        // relu(agg + b1): lane holds channels 2*lane, 2*lane+1
        float vx = fmaxf(acc.x * inv + b1s[2 * lane],     0.f);
        float vy = fmaxf(acc.y * inv + b1s[2 * lane + 1], 0.f);
        // gemm2: h2[c] = sum_k v[k] * Wt[k*40+c]
        float o0 = 0.f, o1 = 0.f;
        #pragma unroll
        for (int k = 0; k < 64; k++) {
            float xk = __shfl_sync(0xffffffffu, (k & 1) ? vy : vx, k >> 1);
            o0 = fmaf(Wt[k * 40 + lane], xk, o0);
            if (lane < 8) o1 = fmaf(Wt[k * 40 + 32 + lane], xk, o1);
        }
        g_h2[(size_t)dst * 40 + lane] = o0;
        if (lane < 8) g_h2[(size_t)dst * 40 + 32 + lane] = o1;
        // alpha2
        float ps = o0 * sa[lane] + (lane < 8 ? o1 * sa[32 + lane] : 0.f);
        float pd = o0 * sd[lane] + (lane < 8 ? o1 * sd[32 + lane] : 0.f);
        #pragma unroll
        for (int off = 16; off; off >>= 1) {
            ps += __shfl_xor_sync(0xffffffffu, ps, off);
            pd += __shfl_xor_sync(0xffffffffu, pd, off);
        }
        if (lane == 0) { g_as2[dst] = ps; g_ad2[dst] = pd; }
    }
}

// ------ layer2 fused: softmax-aggregate + bias + log_softmax -> out ----------
__global__ void k_agg2f(const float* __restrict__ b2, float* __restrict__ out, int n) {
    __shared__ float es[8][32];
    __shared__ int   ss[8][32];
    int tid = threadIdx.x;
    int w = tid >> 5, lane = tid & 31;
    int ngroups = gridDim.x * 8;

    float b2a = __ldg(&b2[lane]);
    float b2b = (lane < 8) ? __ldg(&b2[32 + lane]) : 0.f;

    for (int dst = blockIdx.x * 8 + w; dst < n; dst += ngroups) {
        int row = g_rowstart[dst], end = g_rowstart[dst + 1];
        float ad = g_ad2[dst];
        float acc0 = 0.f, acc1 = 0.f, den = 0.f;

        for (int base = row; base < end; base += 32) {
            int k = base + lane;
            float e = 0.f;
            int s = 0;
            if (k < end) {
                s = g_srcs[k];
                e = __expf(lrelu(g_as2[s] + ad));
                den += e;
            }
            ss[w][lane] = s;
            es[w][lane] = e;
            __syncwarp();
            int m = min(32, end - base);
            #pragma unroll 4
            for (int k2 = 0; k2 < m; k2++) {
                int s2   = ss[w][k2];
                float ek = es[w][k2];
                acc0 = fmaf(ek, g_h2[(size_t)s2 * 40 + lane], acc0);
                if (lane < 8) acc1 = fmaf(ek, g_h2[(size_t)s2 * 40 + 32 + lane], acc1);
            }
            __syncwarp();
        }
        #pragma unroll
        for (int off = 16; off; off >>= 1) den += __shfl_xor_sync(0xffffffffu, den, off);
        float inv = __frcp_rn(den);
        // bias + log_softmax over 40 classes
        float v0 = acc0 * inv + b2a;
        float v1 = (lane < 8) ? (acc1 * inv + b2b) : -1e30f;
        float m = fmaxf(v0, v1);
        #pragma unroll
        for (int off = 16; off; off >>= 1) m = fmaxf(m, __shfl_xor_sync(0xffffffffu, m, off));
        float s = __expf(v0 - m) + (lane < 8 ? __expf(v1 - m) : 0.f);
        #pragma unroll
        for (int off = 16; off; off >>= 1) s += __shfl_xor_sync(0xffffffffu, s, off);
        float ls = m + logf(s);
        out[(size_t)dst * 40 + lane] = v0 - ls;
        if (lane < 8) out[(size_t)dst * 40 + 32 + lane] = v1 - ls;
    }
}

// ---------------- launcher ---------------------------------------------------
extern "C" void kernel_launch(void* const* d_in, const int* in_sizes, int n_in,
                              void* d_out, int out_size) {
    const float* x      = (const float*)d_in[0];
    const int*   ei     = (const int*)  d_in[1];
    const float* W1     = (const float*)d_in[2];
    const float* a_src1 = (const float*)d_in[3];
    const float* a_dst1 = (const float*)d_in[4];
    const float* b1     = (const float*)d_in[5];
    const float* W2     = (const float*)d_in[6];
    const float* a_src2 = (const float*)d_in[7];
    const float* a_dst2 = (const float*)d_in[8];
    const float* b2     = (const float*)d_in[9];
    float* out = (float*)d_out;

    int n = in_sizes[0] / 128;
    int e = in_sizes[1] / 2;
    int T = e + n;
    int nb = (n + 1023) >> 10;

    // CSR build (dst-sorted), parallel scan
    k_zero_deg <<<(n + 255) / 256, 256>>>(n);
    k_hist     <<<(T + 255) / 256, 256>>>(ei, e, n);
    k_blocksum <<<nb, 256>>>();
    k_scanb    <<<1, 1024>>>(nb, n);
    k_writerow <<<nb, 256>>>();
    k_scatter  <<<(T + 255) / 256, 256>>>(ei, e, n);
    // layer 1
    k_gemm1    <<<(n + G1_TM - 1) / G1_TM, 256>>>(x, W1, n);
    k_alpha1   <<<(n * 32 + 255) / 256, 256>>>(a_src1, a_dst1, n);
    k_agg1f    <<<1184, 256>>>(b1, W2, a_src2, a_dst2, n);
    // layer 2 (fused log-softmax)
    k_agg2f    <<<1184, 256>>>(b2, out, n);
}

// round 7
// speedup vs baseline: 1.6877x; 1.0658x over previous
#include <cuda_runtime.h>
#include <math.h>

#define MAXN 100000
#define MAXE 1600000
#define MAXT (MAXN + MAXE)
#define NB_MAX 1024

// ---------------- static device scratch -------------------------------------
__device__ __align__(16) float g_h1  [MAXN * 64];
__device__ __align__(16) float g_as1 [MAXN * 4];
__device__ __align__(16) float g_ad1 [MAXN * 4];
__device__ __align__(16) float g_h2  [MAXN * 40];
__device__            float g_as2 [MAXN];
__device__            float g_ad2 [MAXN];
// CSR structures (rebuilt every launch; dst-sorted). Padded so int4/scan code
// never needs bounds checks: pad region is never written and stays zero.
__device__ int g_deg     [MAXN + 1024];
__device__ int g_rowstart[MAXN + 1024];
__device__ int g_cursor  [MAXN + 1024];
__device__ int g_srcs    [MAXT];
__device__ int g_bsum[NB_MAX];
__device__ int g_boff[NB_MAX];

__device__ __forceinline__ float lrelu(float v) { return v > 0.f ? v : 0.2f * v; }

// ---------------- CSR build --------------------------------------------------
__global__ void k_zero_deg(int n) {
    int i = blockIdx.x * blockDim.x + threadIdx.x;
    if (i < n) g_deg[i] = 0;
}

__global__ void k_hist(const int* __restrict__ ei, int e, int n) {
    int t = blockIdx.x * blockDim.x + threadIdx.x;
    if (t >= e + n) return;
    int dst = (t < e) ? __ldg(&ei[e + t]) : (t - e);
    atomicAdd(&g_deg[dst], 1);
}

__global__ void k_blocksum() {
    __shared__ int wsum[8];
    int b = blockIdx.x, tid = threadIdx.x;
    int4 d = *(const int4*)&g_deg[b * 1024 + tid * 4];
    int s = d.x + d.y + d.z + d.w;
    #pragma unroll
    for (int off = 16; off; off >>= 1) s += __shfl_down_sync(0xffffffffu, s, off);
    if ((tid & 31) == 0) wsum[tid >> 5] = s;
    __syncthreads();
    if (tid == 0) {
        int t = 0;
        #pragma unroll
        for (int i = 0; i < 8; i++) t += wsum[i];
        g_bsum[b] = t;
    }
}

__global__ void k_scanb(int nb, int n) {
    __shared__ int sm[1024];
    int tid = threadIdx.x;
    int v = (tid < nb) ? g_bsum[tid] : 0;
    sm[tid] = v;
    __syncthreads();
    for (int off = 1; off < 1024; off <<= 1) {
        int a = (tid >= off) ? sm[tid - off] : 0;
        __syncthreads();
        sm[tid] += a;
        __syncthreads();
    }
    if (tid < nb) g_boff[tid] = sm[tid] - v;
    if (tid == 1023) g_rowstart[n] = sm[1023];
}

__global__ void k_writerow() {
    __shared__ int tsum[256];
    int b = blockIdx.x, tid = threadIdx.x;
    int idx = b * 1024 + tid * 4;
    int4 d = *(const int4*)&g_deg[idx];
    int s = d.x + d.y + d.z + d.w;
    tsum[tid] = s;
    __syncthreads();
    for (int off = 1; off < 256; off <<= 1) {
        int a = (tid >= off) ? tsum[tid - off] : 0;
        __syncthreads();
        tsum[tid] += a;
        __syncthreads();
    }
    int r = tsum[tid] - s + g_boff[b];
    g_rowstart[idx] = r;     g_cursor[idx] = r;     r += d.x;
    g_rowstart[idx + 1] = r; g_cursor[idx + 1] = r; r += d.y;
    g_rowstart[idx + 2] = r; g_cursor[idx + 2] = r; r += d.z;
    g_rowstart[idx + 3] = r; g_cursor[idx + 3] = r;
}

__global__ void k_scatter(const int* __restrict__ ei, int e, int n) {
    int t = blockIdx.x * blockDim.x + threadIdx.x;
    if (t >= e + n) return;
    int src, dst;
    if (t < e) { src = __ldg(&ei[t]); dst = __ldg(&ei[e + t]); } else { src = dst = t - e; }
    int pos = atomicAdd(&g_cursor[dst], 1);
    g_srcs[pos] = src;
}

// ------- tiled GEMM1 + fused alpha1: h1 = x @ W1^T, as1/ad1 = h1·a ----------
#define G1_TM 64
__global__ void k_gemm1(const float* __restrict__ x, const float* __restrict__ W1,
                        const float* __restrict__ a_s, const float* __restrict__ a_d,
                        int n) {
    __shared__ float As[G1_TM * 68];
    __shared__ float Bs[64 * 64];
    int tid = threadIdx.x;
    int row0 = blockIdx.x * G1_TM;
    int tr = tid >> 4, tc = tid & 15;

    float acc[4][4] = {};
    const float4* Bs4 = (const float4*)Bs;

    #pragma unroll
    for (int kt = 0; kt < 2; kt++) {
        for (int i = tid; i < 64 * 64; i += 256) {
            int c = i >> 6, kk = i & 63;
            Bs[kk * 64 + c] = W1[c * 128 + kt * 64 + kk];
        }
        for (int i = tid; i < G1_TM * 16; i += 256) {
            int r = i >> 4, k4 = i & 15;
            int row = row0 + r;
            float4 v = (row < n) ? *(const float4*)&x[(size_t)row * 128 + kt * 64 + k4 * 4]
                                 : make_float4(0.f, 0.f, 0.f, 0.f);
            *(float4*)&As[r * 68 + k4 * 4] = v;
        }
        __syncthreads();

        #pragma unroll 4
        for (int k = 0; k < 64; k++) {
            float a0 = As[(tr * 4 + 0) * 68 + k];
            float a1 = As[(tr * 4 + 1) * 68 + k];
            float a2 = As[(tr * 4 + 2) * 68 + k];
            float a3 = As[(tr * 4 + 3) * 68 + k];
            float4 b = Bs4[k * 16 + tc];
            acc[0][0] = fmaf(a0, b.x, acc[0][0]); acc[0][1] = fmaf(a0, b.y, acc[0][1]);
            acc[0][2] = fmaf(a0, b.z, acc[0][2]); acc[0][3] = fmaf(a0, b.w, acc[0][3]);
            acc[1][0] = fmaf(a1, b.x, acc[1][0]); acc[1][1] = fmaf(a1, b.y, acc[1][1]);
            acc[1][2] = fmaf(a1, b.z, acc[1][2]); acc[1][3] = fmaf(a1, b.w, acc[1][3]);
            acc[2][0] = fmaf(a2, b.x, acc[2][0]); acc[2][1] = fmaf(a2, b.y, acc[2][1]);
            acc[2][2] = fmaf(a2, b.z, acc[2][2]); acc[2][3] = fmaf(a2, b.w, acc[2][3]);
            acc[3][0] = fmaf(a3, b.x, acc[3][0]); acc[3][1] = fmaf(a3, b.y, acc[3][1]);
            acc[3][2] = fmaf(a3, b.z, acc[3][2]); acc[3][3] = fmaf(a3, b.w, acc[3][3]);
        }
        __syncthreads();
    }

    int col = tc * 4;
    #pragma unroll
    for (int i = 0; i < 4; i++) {
        int row = row0 + tr * 4 + i;
        if (row < n)
            *(float4*)&g_h1[(size_t)row * 64 + col] =
                make_float4(acc[i][0], acc[i][1], acc[i][2], acc[i][3]);
    }

    // fused alpha: thread covers cols [col, col+4) — all in head = tc>>2.
    float as0 = a_s[col], as1v = a_s[col + 1], as2v = a_s[col + 2], as3 = a_s[col + 3];
    float ad0 = a_d[col], ad1v = a_d[col + 1], ad2v = a_d[col + 2], ad3 = a_d[col + 3];
    float ps[4], pd[4];
    #pragma unroll
    for (int i = 0; i < 4; i++) {
        ps[i] = acc[i][0] * as0 + acc[i][1] * as1v + acc[i][2] * as2v + acc[i][3] * as3;
        pd[i] = acc[i][0] * ad0 + acc[i][1] * ad1v + acc[i][2] * ad2v + acc[i][3] * ad3;
    }
    // reduce over the 4 tc-lanes of the same head (lane bits 0,1)
    #pragma unroll
    for (int off = 1; off <= 2; off <<= 1) {
        #pragma unroll
        for (int i = 0; i < 4; i++) {
            ps[i] += __shfl_xor_sync(0xffffffffu, ps[i], off);
            pd[i] += __shfl_xor_sync(0xffffffffu, pd[i], off);
        }
    }
    if ((tc & 3) == 0) {
        int head = tc >> 2;
        #pragma unroll
        for (int i = 0; i < 4; i++) {
            int row = row0 + tr * 4 + i;
            if (row < n) {
                g_as1[row * 4 + head] = ps[i];
                g_ad1[row * 4 + head] = pd[i];
            }
        }
    }
}

// ------ layer1 fused: softmax-aggregate + relu+bias + gemm2 + alpha2 ---------
__global__ void k_agg1f(const float* __restrict__ b1, const float* __restrict__ W2,
                        const float* __restrict__ a_s2, const float* __restrict__ a_d2,
                        int n) {
    __shared__ float Wt[64 * 40];
    __shared__ float sa[40], sd[40], b1s[64];
    __shared__ __align__(16) float es[8][128];
    __shared__ int ss[8][32];
    int tid = threadIdx.x;
    for (int i = tid; i < 40 * 64; i += 256) {
        int c = i / 64, k = i - c * 64;
        Wt[k * 40 + c] = W2[i];
    }
    if (tid < 40) { sa[tid] = a_s2[tid]; sd[tid] = a_d2[tid]; }
    if (tid < 64) b1s[tid] = b1[tid];
    __syncthreads();

    int w = tid >> 5, lane = tid & 31;
    int head = lane >> 3;
    int ngroups = gridDim.x * 8;

    for (int dst = blockIdx.x * 8 + w; dst < n; dst += ngroups) {
        int row = g_rowstart[dst], end = g_rowstart[dst + 1];
        float4 ad = *(const float4*)&g_ad1[dst * 4];
        float2 acc = make_float2(0.f, 0.f);
        float4 den = make_float4(0.f, 0.f, 0.f, 0.f);

        for (int base = row; base < end; base += 32) {
            int k = base + lane;
            float4 e4 = make_float4(0.f, 0.f, 0.f, 0.f);
            int s = 0;
            if (k < end) {
                s = g_srcs[k];
                float4 as = *(const float4*)&g_as1[s * 4];
                e4.x = __expf(lrelu(as.x + ad.x));
                e4.y = __expf(lrelu(as.y + ad.y));
                e4.z = __expf(lrelu(as.z + ad.z));
                e4.w = __expf(lrelu(as.w + ad.w));
                den.x += e4.x; den.y += e4.y; den.z += e4.z; den.w += e4.w;
            }
            ss[w][lane] = s;
            *(float4*)&es[w][lane * 4] = e4;
            __syncwarp();
            int m = min(32, end - base);
            #pragma unroll 4
            for (int k2 = 0; k2 < m; k2++) {
                int s2   = ss[w][k2];
                float ek = es[w][k2 * 4 + head];
                float2 h = *(const float2*)&g_h1[(size_t)s2 * 64 + lane * 2];
                acc.x = fmaf(ek, h.x, acc.x);
                acc.y = fmaf(ek, h.y, acc.y);
            }
            __syncwarp();
        }
        #pragma unroll
        for (int off = 16; off; off >>= 1) {
            den.x += __shfl_xor_sync(0xffffffffu, den.x, off);
            den.y += __shfl_xor_sync(0xffffffffu, den.y, off);
            den.z += __shfl_xor_sync(0xffffffffu, den.z, off);
            den.w += __shfl_xor_sync(0xffffffffu, den.w, off);
        }
        float d   = head == 0 ? den.x : head == 1 ? den.y : head == 2 ? den.z : den.w;
        float inv = __frcp_rn(d);
        float vx = fmaxf(acc.x * inv + b1s[2 * lane],     0.f);
        float vy = fmaxf(acc.y * inv + b1s[2 * lane + 1], 0.f);
        float o0 = 0.f, o1 = 0.f;
        #pragma unroll
        for (int k = 0; k < 64; k++) {
            float xk = __shfl_sync(0xffffffffu, (k & 1) ? vy : vx, k >> 1);
            o0 = fmaf(Wt[k * 40 + lane], xk, o0);
            if (lane < 8) o1 = fmaf(Wt[k * 40 + 32 + lane], xk, o1);
        }
        g_h2[(size_t)dst * 40 + lane] = o0;
        if (lane < 8) g_h2[(size_t)dst * 40 + 32 + lane] = o1;
        float ps = o0 * sa[lane] + (lane < 8 ? o1 * sa[32 + lane] : 0.f);
        float pd = o0 * sd[lane] + (lane < 8 ? o1 * sd[32 + lane] : 0.f);
        #pragma unroll
        for (int off = 16; off; off >>= 1) {
            ps += __shfl_xor_sync(0xffffffffu, ps, off);
            pd += __shfl_xor_sync(0xffffffffu, pd, off);
        }
        if (lane == 0) { g_as2[dst] = ps; g_ad2[dst] = pd; }
    }
}

// ------ layer2 fused: softmax-aggregate + bias + log_softmax -> out ----------
__global__ void k_agg2f(const float* __restrict__ b2, float* __restrict__ out, int n) {
    __shared__ float es[8][32];
    __shared__ int   ss[8][32];
    int tid = threadIdx.x;
    int w = tid >> 5, lane = tid & 31;
    int ngroups = gridDim.x * 8;

    float b2a = __ldg(&b2[lane]);
    float b2b = (lane < 8) ? __ldg(&b2[32 + lane]) : 0.f;

    for (int dst = blockIdx.x * 8 + w; dst < n; dst += ngroups) {
        int row = g_rowstart[dst], end = g_rowstart[dst + 1];
        float ad = g_ad2[dst];
        float acc0 = 0.f, acc1 = 0.f, den = 0.f;

        for (int base = row; base < end; base += 32) {
            int k = base + lane;
            float e = 0.f;
            int s = 0;
            if (k < end) {
                s = g_srcs[k];
                e = __expf(lrelu(g_as2[s] + ad));
                den += e;
            }
            ss[w][lane] = s;
            es[w][lane] = e;
            __syncwarp();
            int m = min(32, end - base);
            #pragma unroll 4
            for (int k2 = 0; k2 < m; k2++) {
                int s2   = ss[w][k2];
                float ek = es[w][k2];
                acc0 = fmaf(ek, g_h2[(size_t)s2 * 40 + lane], acc0);
                if (lane < 8) acc1 = fmaf(ek, g_h2[(size_t)s2 * 40 + 32 + lane], acc1);
            }
            __syncwarp();
        }
        #pragma unroll
        for (int off = 16; off; off >>= 1) den += __shfl_xor_sync(0xffffffffu, den, off);
        float inv = __frcp_rn(den);
        float v0 = acc0 * inv + b2a;
        float v1 = (lane < 8) ? (acc1 * inv + b2b) : -1e30f;
        float m = fmaxf(v0, v1);
        #pragma unroll
        for (int off = 16; off; off >>= 1) m = fmaxf(m, __shfl_xor_sync(0xffffffffu, m, off));
        float s = __expf(v0 - m) + (lane < 8 ? __expf(v1 - m) : 0.f);
        #pragma unroll
        for (int off = 16; off; off >>= 1) s += __shfl_xor_sync(0xffffffffu, s, off);
        float ls = m + logf(s);
        out[(size_t)dst * 40 + lane] = v0 - ls;
        if (lane < 8) out[(size_t)dst * 40 + 32 + lane] = v1 - ls;
    }
}

// ---------------- launcher ---------------------------------------------------
extern "C" void kernel_launch(void* const* d_in, const int* in_sizes, int n_in,
                              void* d_out, int out_size) {
    const float* x      = (const float*)d_in[0];
    const int*   ei     = (const int*)  d_in[1];
    const float* W1     = (const float*)d_in[2];
    const float* a_src1 = (const float*)d_in[3];
    const float* a_dst1 = (const float*)d_in[4];
    const float* b1     = (const float*)d_in[5];
    const float* W2     = (const float*)d_in[6];
    const float* a_src2 = (const float*)d_in[7];
    const float* a_dst2 = (const float*)d_in[8];
    const float* b2     = (const float*)d_in[9];
    float* out = (float*)d_out;

    int n = in_sizes[0] / 128;
    int e = in_sizes[1] / 2;
    int T = e + n;
    int nb = (n + 1023) >> 10;

    // Fork a second stream for the CSR build (independent of gemm1 chain).
    // Stream/events intentionally NOT destroyed: destroying a stream that
    // participates in an active graph capture would invalidate the capture.
    // kernel_launch is called only a handful of times, so the leak is bounded.
    cudaStream_t s2;
    cudaStreamCreateWithFlags(&s2, cudaStreamNonBlocking);
    cudaEvent_t evFork, evJoin;
    cudaEventCreateWithFlags(&evFork, cudaEventDisableTiming);
    cudaEventCreateWithFlags(&evJoin, cudaEventDisableTiming);

    cudaEventRecord(evFork, 0);
    cudaStreamWaitEvent(s2, evFork, 0);

    // CSR build on s2
    k_zero_deg <<<(n + 255) / 256, 256, 0, s2>>>(n);
    k_hist     <<<(T + 255) / 256, 256, 0, s2>>>(ei, e, n);
    k_blocksum <<<nb, 256, 0, s2>>>();
    k_scanb    <<<1, 1024, 0, s2>>>(nb, n);
    k_writerow <<<nb, 256, 0, s2>>>();
    k_scatter  <<<(T + 255) / 256, 256, 0, s2>>>(ei, e, n);
    cudaEventRecord(evJoin, s2);

    // gemm1 (+fused alpha1) on the main stream, concurrent with CSR build
    k_gemm1    <<<(n + G1_TM - 1) / G1_TM, 256>>>(x, W1, a_src1, a_dst1, n);

    // join: agg needs both CSR and h1/alpha
    cudaStreamWaitEvent(0, evJoin, 0);
    k_agg1f    <<<1184, 256>>>(b1, W2, a_src2, a_dst2, n);
    k_agg2f    <<<1184, 256>>>(b2, out, n);
}